// round 13
// baseline (speedup 1.0000x reference)
#include <cuda_runtime.h>
#include <cuda_fp16.h>
#include <cstdint>

// ---------------- problem constants ----------------
#define N_AG 2048
#define T_K 16
#define D_F 10
#define E_F 128
#define H_F 512
#define M3 (E_F * D_F)      // 1280
#define ND (N_AG * D_F)
#define NPTS 60
#define NE (N_AG * E_F)

// ---------------- scratch ----------------
__device__ float g_M[T_K * ND];
__device__ float g_dX[NPTS * ND];
__device__ float g_z[NE];
__device__ float g_k1[NE];
__device__ float g_k2[NE];
__device__ float g_k3[NE];
__device__ float g_b3p[M3];

#define H16A __device__ __align__(16) __half
H16A g_zh[NE];
H16A g_zinh[NE];
H16A g_y0[N_AG * H_F];
H16A g_y1[N_AG * H_F];
H16A g_y2[N_AG * H_F];
H16A g_W0[H_F * E_F];
H16A g_W1[H_F * H_F];
H16A g_W2[H_F * H_F];
H16A g_W3[M3 * H_F];               // rows permuted: dst row = d*128+e

// ---------------- helpers ----------------
__device__ __forceinline__ uint32_t smem_u32(const void* p) {
    uint32_t a;
    asm("{ .reg .u64 t; cvta.to.shared.u64 t, %1; cvt.u32.u64 %0, t; }" : "=r"(a) : "l"(p));
    return a;
}
__device__ __forceinline__ void cp16(uint32_t s, const void* g) {
    asm volatile("cp.async.cg.shared.global [%0], [%1], 16;" :: "r"(s), "l"(g));
}
__device__ __forceinline__ void ldsm4(uint32_t& r0, uint32_t& r1, uint32_t& r2, uint32_t& r3,
                                      uint32_t a) {
    asm volatile("ldmatrix.sync.aligned.m8n8.x4.shared.b16 {%0,%1,%2,%3}, [%4];"
                 : "=r"(r0), "=r"(r1), "=r"(r2), "=r"(r3) : "r"(a));
}
__device__ __forceinline__ void mma16816(float& c0, float& c1, float& c2, float& c3,
                                         uint32_t a0, uint32_t a1, uint32_t a2, uint32_t a3,
                                         uint32_t b0, uint32_t b1) {
    asm volatile("mma.sync.aligned.m16n8k16.row.col.f32.f16.f16.f32 "
                 "{%0,%1,%2,%3},{%4,%5,%6,%7},{%8,%9},{%0,%1,%2,%3};"
                 : "+f"(c0), "+f"(c1), "+f"(c2), "+f"(c3)
                 : "r"(a0), "r"(a1), "r"(a2), "r"(a3), "r"(b0), "r"(b1));
}
__device__ __forceinline__ float fast_tanh(float x) {
    x = fminf(fmaxf(x, -15.f), 15.f);
    float e = __expf(-2.f * x);
    return (1.f - e) * __frcp_rn(1.f + e);
}

// smem per stage buffer (H-layer GEMMs): STRIDE 40 halves. A(64) 5120 B + B(64) 5120 B.
#define STRIDE 40
#define OFF_A  0
#define OFF_B  5120
#define BUF_B  10240
#define NSTAGE 4
#define SMEM_BYTES (NSTAGE * BUF_B)      // 40960

// ---------------- fp16 HMMA GEMM (R11 geometry): relu, fp16 out ----------------
// CTA 64x64, BK=32, 8 warps 4(M)x2(N), warp tile 16x32, ldmatrix feeds.
__global__ void __launch_bounds__(256) mma_gemm(
    const __half* __restrict__ A, const __half* __restrict__ Bw,
    const float* __restrict__ bias,
    __half* __restrict__ Ch, int K, int Mout)
{
    extern __shared__ char smem[];
    const uint32_t sb = smem_u32(smem);
    const int tid = threadIdx.x, wid = tid >> 5, lid = tid & 31;
    const int rowBase = blockIdx.y * 64;
    const int colBase = blockIdx.x * 64;
    const int warpM = (wid & 3) * 16;
    const int warpN = (wid >> 2) * 32;
    const int grp = lid >> 2, q = lid & 3;

    const int ar  = tid >> 2;            // row 0..63
    const int acb = (tid & 3) * 8;       // half offset

    const __half* gA = A  + (size_t)(rowBase + ar) * K + acb;
    const __half* gB = Bw + (size_t)(colBase + ar) * K + acb;
    const uint32_t sA = sb + OFF_A + (ar * STRIDE + acb) * 2;
    const uint32_t sB = sb + OFF_B + (ar * STRIDE + acb) * 2;

    const int sel  = lid >> 3;
    const int lrow = (sel & 1) * 8 + (lid & 7);
    const int lcol = (sel >> 1) * 8;
    const uint32_t aoff  = ((warpM + lrow) * STRIDE + lcol) * 2;
    const uint32_t boff0 = ((warpN + lrow) * STRIDE + lcol) * 2;
    const uint32_t boff1 = ((warpN + 16 + lrow) * STRIDE + lcol) * 2;

    float c[4][4];
#pragma unroll
    for (int ni = 0; ni < 4; ni++)
#pragma unroll
        for (int r = 0; r < 4; r++) c[ni][r] = 0.f;

    const int NK = K >> 5;
#pragma unroll
    for (int s = 0; s < NSTAGE - 1; s++) {
        if (s < NK) {
            const int k0 = s << 5;
            const uint32_t bo = s * BUF_B;
            cp16(sA + bo, gA + k0);
            cp16(sB + bo, gB + k0);
        }
        asm volatile("cp.async.commit_group;");
    }

    for (int kt = 0; kt < NK; kt++) {
        asm volatile("cp.async.wait_group %0;" :: "n"(NSTAGE - 2));
        __syncthreads();
        if (kt + NSTAGE - 1 < NK) {
            const int k0 = (kt + NSTAGE - 1) << 5;
            const uint32_t bo = ((kt + NSTAGE - 1) & (NSTAGE - 1)) * BUF_B;
            cp16(sA + bo, gA + k0);
            cp16(sB + bo, gB + k0);
        }
        asm volatile("cp.async.commit_group;");

        const uint32_t aBase = sb + (kt & (NSTAGE - 1)) * BUF_B;
#pragma unroll
        for (int kk = 0; kk < 32; kk += 16) {
            const uint32_t kb = kk * 2;
            uint32_t a[4], b[4][2];
            ldsm4(a[0], a[1], a[2], a[3],             aBase + OFF_A + aoff + kb);
            ldsm4(b[0][0], b[1][0], b[0][1], b[1][1], aBase + OFF_B + boff0 + kb);
            ldsm4(b[2][0], b[3][0], b[2][1], b[3][1], aBase + OFF_B + boff1 + kb);
#pragma unroll
            for (int ni = 0; ni < 4; ni++)
                mma16816(c[ni][0], c[ni][1], c[ni][2], c[ni][3],
                         a[0], a[1], a[2], a[3], b[ni][0], b[ni][1]);
        }
    }

#pragma unroll
    for (int ni = 0; ni < 4; ni++) {
        const int col = colBase + warpN + ni * 8 + q * 2;
        const float bv0 = bias[col], bv1 = bias[col + 1];
        const int row0 = rowBase + warpM + grp;
        float v00 = fmaxf(c[ni][0] + bv0, 0.f), v01 = fmaxf(c[ni][1] + bv1, 0.f);
        float v10 = fmaxf(c[ni][2] + bv0, 0.f), v11 = fmaxf(c[ni][3] + bv1, 0.f);
        __half2 H0 = __floats2half2_rn(v00, v01);
        __half2 H1 = __floats2half2_rn(v10, v11);
        *(uint32_t*)(Ch + (size_t)row0 * Mout + col) = *(uint32_t*)&H0;
        *(uint32_t*)(Ch + (size_t)(row0 + 8) * Mout + col) = *(uint32_t*)&H1;
    }
}

// ================= L3 fused: GEMM + tanh + einsum over d + RK combine ===============
// CTA: 32 rows x 64 e-cols. Loops 10 d-tiles (W3 permuted: row d*128+e), kv in regs.
// grid (2 e-tiles, 64 n-tiles) = 128 CTAs, 256 thr, 8 warps 2(M)x4(N), warp 16x16.
#define A3_STRIDE 520
#define A3_BYTES  (32 * A3_STRIDE * 2)   // 33280
#define B3_TILE   5120                   // 64 x 40 x 2
#define SMEM3_BYTES (A3_BYTES + NSTAGE * B3_TILE)   // 53760

__global__ void __launch_bounds__(256) l3_combine(
    const __half* __restrict__ A, const __half* __restrict__ W3,
    const float* __restrict__ bias, const float* __restrict__ dx,
    const float* __restrict__ t, int k, int stage)
{
    extern __shared__ char smem[];
    const uint32_t sb = smem_u32(smem);
    const int tid = threadIdx.x, wid = tid >> 5, lid = tid & 31;
    const int rowBase = blockIdx.y * 32;
    const int eBase = blockIdx.x * 64;
    const int warpM = (wid & 1) * 16;
    const int warpN = (wid >> 1) * 16;
    const int grp = lid >> 2, q = lid & 3;

    // ---- load A (y2: 32 rows x 512) into persistent smem ----
    {
        const int row = tid >> 3;
        const int c0 = tid & 7;
        const __half* gA = A + (size_t)(rowBase + row) * H_F;
        const uint32_t sA = sb + (row * A3_STRIDE) * 2;
#pragma unroll
        for (int j = 0; j < 8; j++) {
            const int ch = c0 + 8 * j;
            cp16(sA + ch * 16, gA + ch * 8);
        }
    }

    // ---- B loads: thread -> one 16B chunk per tile ----
    const int brow = tid >> 2;
    const int bch  = (tid & 3) * 8;
    const uint32_t sB0 = sb + A3_BYTES + (brow * STRIDE + bch) * 2;

    // ldmatrix addressing
    const int sel  = lid >> 3;
    const int lrow = (sel & 1) * 8 + (lid & 7);
    const int lcol = (sel >> 1) * 8;
    const uint32_t aoff = ((warpM + lrow) * A3_STRIDE + lcol) * 2;
    const uint32_t boff = ((warpN + lrow) * STRIDE + lcol) * 2;

    const int NIT = D_F * (H_F / 32);   // 160

    // prologue: iters 0..2 (group 0 also carries the A loads)
#pragma unroll
    for (int s = 0; s < NSTAGE - 1; s++) {
        const int d = s >> 4, kt = s & 15;
        const __half* gB = W3 + (size_t)(d * E_F + eBase + brow) * H_F + kt * 32 + bch;
        cp16(sB0 + s * B3_TILE, gB);
        asm volatile("cp.async.commit_group;");
    }

    float c[2][4], kv[2][4];
#pragma unroll
    for (int ni = 0; ni < 2; ni++)
#pragma unroll
        for (int r = 0; r < 4; r++) { c[ni][r] = 0.f; kv[ni][r] = 0.f; }

    const int row0 = rowBase + warpM + grp;
    const int pt_base = 0;  // dx already offset by caller
    (void)pt_base;

    for (int it = 0; it < NIT; it++) {
        asm volatile("cp.async.wait_group %0;" :: "n"(NSTAGE - 2));
        __syncthreads();

        if (it + NSTAGE - 1 < NIT) {
            const int nx = it + NSTAGE - 1;
            const int d = nx >> 4, kt = nx & 15;
            const __half* gB = W3 + (size_t)(d * E_F + eBase + brow) * H_F + kt * 32 + bch;
            cp16(sB0 + (nx & (NSTAGE - 1)) * B3_TILE, gB);
        }
        asm volatile("cp.async.commit_group;");

        const int d  = it >> 4;
        const int kt = it & 15;
        const uint32_t bBase = sb + A3_BYTES + (it & (NSTAGE - 1)) * B3_TILE;
        const uint32_t aCol  = kt * 32;
#pragma unroll
        for (int kk = 0; kk < 32; kk += 16) {
            uint32_t a[4], b[2][2];
            ldsm4(a[0], a[1], a[2], a[3],             sb + aoff + (aCol + kk) * 2);
            ldsm4(b[0][0], b[1][0], b[0][1], b[1][1], bBase + boff + kk * 2);
#pragma unroll
            for (int ni = 0; ni < 2; ni++)
                mma16816(c[ni][0], c[ni][1], c[ni][2], c[ni][3],
                         a[0], a[1], a[2], a[3], b[ni][0], b[ni][1]);
        }

        if (kt == 15) {   // finalize this d
            const float dx0 = dx[row0 * D_F + d];
            const float dx1 = dx[(row0 + 8) * D_F + d];
#pragma unroll
            for (int ni = 0; ni < 2; ni++) {
                const int e = eBase + warpN + ni * 8 + q * 2;
                const float bv0 = bias[d * E_F + e], bv1 = bias[d * E_F + e + 1];
                kv[ni][0] += fast_tanh(c[ni][0] + bv0) * dx0;
                kv[ni][1] += fast_tanh(c[ni][1] + bv1) * dx0;
                kv[ni][2] += fast_tanh(c[ni][2] + bv0) * dx1;
                kv[ni][3] += fast_tanh(c[ni][3] + bv1) * dx1;
                c[ni][0] = 0.f; c[ni][1] = 0.f; c[ni][2] = 0.f; c[ni][3] = 0.f;
            }
        }
    }

    // ---- RK combine (no atomics: this CTA owns its (n,e) block) ----
    const float hs = t[k + 1] - t[k];
#pragma unroll
    for (int ni = 0; ni < 2; ni++) {
        const int e = eBase + warpN + ni * 8 + q * 2;
#pragma unroll
        for (int rr = 0; rr < 2; rr++) {
            const int row = row0 + rr * 8;
            const int idx = row * E_F + e;
            const float ka = kv[ni][rr * 2], kb = kv[ni][rr * 2 + 1];
            float2 z = *(const float2*)&g_z[idx];
            float zn0, zn1;
            if (stage == 0) {
                *(float2*)&g_k1[idx] = make_float2(ka, kb);
                zn0 = z.x + hs * ka / 3.f; zn1 = z.y + hs * kb / 3.f;
            } else if (stage == 1) {
                *(float2*)&g_k2[idx] = make_float2(ka, kb);
                float2 k1v = *(const float2*)&g_k1[idx];
                zn0 = z.x + hs * (ka - k1v.x / 3.f); zn1 = z.y + hs * (kb - k1v.y / 3.f);
            } else if (stage == 2) {
                *(float2*)&g_k3[idx] = make_float2(ka, kb);
                float2 k1v = *(const float2*)&g_k1[idx];
                float2 k2v = *(const float2*)&g_k2[idx];
                zn0 = z.x + hs * (k1v.x - k2v.x + ka); zn1 = z.y + hs * (k1v.y - k2v.y + kb);
            } else {
                float2 k1v = *(const float2*)&g_k1[idx];
                float2 k2v = *(const float2*)&g_k2[idx];
                float2 k3v = *(const float2*)&g_k3[idx];
                zn0 = z.x + hs * (k1v.x + 3.f * (k2v.x + k3v.x) + ka) * 0.125f;
                zn1 = z.y + hs * (k1v.y + 3.f * (k2v.y + k3v.y) + kb) * 0.125f;
                *(float2*)&g_z[idx] = make_float2(zn0, zn1);
            }
            __half2 H = __floats2half2_rn(zn0, zn1);
            if (stage == 3) *(uint32_t*)&g_zh[idx]   = *(uint32_t*)&H;
            else            *(uint32_t*)&g_zinh[idx] = *(uint32_t*)&H;
        }
    }
}

// ---------------- weight rounding ----------------
__global__ void wround_all(const float* __restrict__ W0, const float* __restrict__ W1,
                           const float* __restrict__ W2,
                           __half* __restrict__ h0, __half* __restrict__ h1,
                           __half* __restrict__ h2) {
    int idx = blockIdx.x * blockDim.x + threadIdx.x;
    const int n0 = H_F * E_F, n1 = n0 + H_F * H_F, n2 = n1 + H_F * H_F;
    if (idx < n0)       h0[idx]      = __float2half_rn(W0[idx]);
    else if (idx < n1)  h1[idx - n0] = __float2half_rn(W1[idx - n0]);
    else if (idx < n2)  h2[idx - n1] = __float2half_rn(W2[idx - n1]);
}
__global__ void wround_w3(const float* __restrict__ s, __half* __restrict__ h,
                          const float* __restrict__ b3) {
    int idx = blockIdx.x * blockDim.x + threadIdx.x;
    if (idx >= M3 * H_F) return;
    int r = idx >> 9, kk = idx & 511;
    int e = r / D_F, d = r - e * D_F;
    h[(size_t)(d * E_F + e) * H_F + kk] = __float2half_rn(s[idx]);
    if (idx < M3) {
        int e2 = idx / D_F, d2 = idx - e2 * D_F;
        g_b3p[d2 * E_F + e2] = b3[idx];
    }
}

// ---------------- spline ----------------
__global__ void spline_kernel(const float* __restrict__ t, const float* __restrict__ x) {
    int col = blockIdx.x * blockDim.x + threadIdx.x;
    if (col >= ND) return;
    int n = col / D_F, d = col % D_F;
    float tv[T_K];
#pragma unroll
    for (int i = 0; i < T_K; i++) tv[i] = t[i];
    float xv[T_K];
#pragma unroll
    for (int i = 0; i < T_K; i++) xv[i] = x[(n * T_K + i) * D_F + d];
    float h[T_K - 1];
#pragma unroll
    for (int i = 0; i < T_K - 1; i++) h[i] = tv[i + 1] - tv[i];
    float cp[T_K], dp[T_K];
    cp[0] = 0.f; dp[0] = 0.f;
#pragma unroll
    for (int i = 1; i < T_K - 1; i++) {
        float rhs = 6.f * ((xv[i + 1] - xv[i]) / h[i] - (xv[i] - xv[i - 1]) / h[i - 1]);
        float m = 2.f * (h[i - 1] + h[i]) - h[i - 1] * cp[i - 1];
        float inv = 1.f / m;
        cp[i] = h[i] * inv;
        dp[i] = (rhs - h[i - 1] * dp[i - 1]) * inv;
    }
    float Mv[T_K];
    Mv[T_K - 1] = 0.f;
#pragma unroll
    for (int i = T_K - 2; i >= 0; i--) Mv[i] = dp[i] - cp[i] * Mv[i + 1];
#pragma unroll
    for (int i = 0; i < T_K; i++) g_M[i * ND + col] = Mv[i];
}

// ---------------- dX/dt ----------------
__global__ void dx_kernel(const float* __restrict__ t, const float* __restrict__ x) {
    int idx = blockIdx.x * blockDim.x + threadIdx.x;
    if (idx >= NPTS * ND) return;
    int pt = idx / ND, col = idx - pt * ND;
    int n = col / D_F, d = col - n * D_F;
    int k = pt >> 2, j = pt & 3;
    float t0 = t[k], t1 = t[k + 1];
    float hs = t1 - t0;
    float s;
    if (j == 0) s = t0;
    else if (j == 1) s = t0 + hs / 3.0f;
    else if (j == 2) s = t0 + 2.0f * hs / 3.0f;
    else s = t1;
    int cnt = 0;
#pragma unroll
    for (int i = 0; i < T_K; i++) cnt += (t[i] <= s) ? 1 : 0;
    int i = min(max(cnt - 1, 0), T_K - 2);
    float hi = t[i + 1] - t[i];
    float xi  = x[(n * T_K + i) * D_F + d];
    float xi1 = x[(n * T_K + i + 1) * D_F + d];
    float Mi  = g_M[i * ND + col];
    float Mi1 = g_M[(i + 1) * ND + col];
    float u = s - t[i];
    float b = (xi1 - xi) / hi - hi * (2.0f * Mi + Mi1) / 6.0f;
    g_dX[idx] = b + Mi * u + (Mi1 - Mi) * (u * u) / (2.0f * hi);
}

// ---------------- z0 ----------------
__global__ void z0_kernel(const float* __restrict__ x, const float* __restrict__ We,
                          const float* __restrict__ be) {
    int idx = blockIdx.x * blockDim.x + threadIdx.x;
    if (idx >= NE) return;
    int n = idx / E_F, e = idx - n * E_F;
    float acc = be[e];
#pragma unroll
    for (int d = 0; d < D_F; d++) acc += x[n * T_K * D_F + d] * We[e * D_F + d];
    g_z[idx] = acc;
    g_zh[idx] = __float2half_rn(acc);
}

// ---------------- output with mask ----------------
__global__ void out_kernel(const int* __restrict__ mask, float* __restrict__ out) {
    int idx = blockIdx.x * blockDim.x + threadIdx.x;
    if (idx >= NE) return;
    int n = idx / E_F;
    out[idx] = (mask[n] != 0) ? g_z[idx] : 0.0f;
}

// ---------------- launcher ----------------
extern "C" void kernel_launch(void* const* d_in, const int* in_sizes, int n_in,
                              void* d_out, int out_size) {
    const float* t  = (const float*)d_in[0];
    const float* x  = (const float*)d_in[1];
    const int*   mask = (const int*)d_in[2];
    const float* We = (const float*)d_in[3];
    const float* be = (const float*)d_in[4];
    const float* W0 = (const float*)d_in[5];
    const float* b0 = (const float*)d_in[6];
    const float* W1 = (const float*)d_in[7];
    const float* b1 = (const float*)d_in[8];
    const float* W2 = (const float*)d_in[9];
    const float* b2 = (const float*)d_in[10];
    const float* W3 = (const float*)d_in[11];
    const float* b3 = (const float*)d_in[12];

    cudaFuncSetAttribute(mma_gemm,   cudaFuncAttributeMaxDynamicSharedMemorySize, SMEM_BYTES);
    cudaFuncSetAttribute(l3_combine, cudaFuncAttributeMaxDynamicSharedMemorySize, SMEM3_BYTES);

    __half *zh, *zinh, *y0, *y1, *y2, *W0r, *W1r, *W2r, *W3r;
    float *b3p, *dXp;
    cudaGetSymbolAddress((void**)&zh, g_zh);
    cudaGetSymbolAddress((void**)&zinh, g_zinh);
    cudaGetSymbolAddress((void**)&y0, g_y0);
    cudaGetSymbolAddress((void**)&y1, g_y1);
    cudaGetSymbolAddress((void**)&y2, g_y2);
    cudaGetSymbolAddress((void**)&W0r, g_W0);    cudaGetSymbolAddress((void**)&W1r, g_W1);
    cudaGetSymbolAddress((void**)&W2r, g_W2);    cudaGetSymbolAddress((void**)&W3r, g_W3);
    cudaGetSymbolAddress((void**)&b3p, g_b3p);
    cudaGetSymbolAddress((void**)&dXp, g_dX);

    const int nW = H_F * E_F + 2 * H_F * H_F;
    wround_all<<<(nW + 255) / 256, 256>>>(W0, W1, W2, W0r, W1r, W2r);
    wround_w3<<<(M3 * H_F + 255) / 256, 256>>>(W3, W3r, b3);

    spline_kernel<<<(ND + 255) / 256, 256>>>(t, x);
    dx_kernel<<<(NPTS * ND + 255) / 256, 256>>>(t, x);
    z0_kernel<<<(NE + 255) / 256, 256>>>(x, We, be);

    dim3 gH(H_F / 64, N_AG / 64);   // (8, 32) = 256 CTAs
    dim3 g3(E_F / 64, N_AG / 32);   // (2, 64) = 128 CTAs
    int eb = (NE + 255) / 256;

    for (int k = 0; k < T_K - 1; k++) {
        for (int stage = 0; stage < 4; stage++) {
            const __half* a0 = (stage == 0) ? zh : zinh;
            mma_gemm<<<gH, 256, SMEM_BYTES>>>(a0, W0r, b0, y0, E_F, H_F);
            mma_gemm<<<gH, 256, SMEM_BYTES>>>(y0, W1r, b1, y1, H_F, H_F);
            mma_gemm<<<gH, 256, SMEM_BYTES>>>(y1, W2r, b2, y2, H_F, H_F);
            l3_combine<<<g3, 256, SMEM3_BYTES>>>(y2, W3r, b3p,
                                                 dXp + (size_t)(k * 4 + stage) * ND,
                                                 t, k, stage);
        }
    }
    out_kernel<<<eb, 256>>>(mask, (float*)d_out);
}

// round 14
// speedup vs baseline: 1.4789x; 1.4789x over previous
#include <cuda_runtime.h>
#include <cuda_fp16.h>
#include <cstdint>

// ---------------- problem constants ----------------
#define N_AG 2048
#define T_K 16
#define D_F 10
#define E_F 128
#define H_F 512
#define M3 (E_F * D_F)      // 1280
#define ND (N_AG * D_F)
#define NPTS 60
#define NE (N_AG * E_F)

// ---------------- scratch ----------------
__device__ float g_M[T_K * ND];
__device__ float g_dX[NPTS * ND];
__device__ float g_z[NE];
__device__ float g_k1[NE];
__device__ float g_k2[NE];
__device__ float g_k3[NE];
__device__ float g_b3p[M3];

#define H16A __device__ __align__(16) __half
H16A g_y3h[N_AG * M3];             // layout [n][d*128+e], fp16
H16A g_zh[NE];
H16A g_zinh[NE];
H16A g_y0[N_AG * H_F];
H16A g_y1[N_AG * H_F];
H16A g_y2[N_AG * H_F];
H16A g_W0[H_F * E_F];
H16A g_W1[H_F * H_F];
H16A g_W2[H_F * H_F];
H16A g_W3[M3 * H_F];               // rows permuted: dst row = d*128+e

// ---------------- helpers ----------------
__device__ __forceinline__ uint32_t smem_u32(const void* p) {
    uint32_t a;
    asm("{ .reg .u64 t; cvta.to.shared.u64 t, %1; cvt.u32.u64 %0, t; }" : "=r"(a) : "l"(p));
    return a;
}
__device__ __forceinline__ void cp16(uint32_t s, const void* g) {
    asm volatile("cp.async.cg.shared.global [%0], [%1], 16;" :: "r"(s), "l"(g));
}
__device__ __forceinline__ void ldsm4(uint32_t& r0, uint32_t& r1, uint32_t& r2, uint32_t& r3,
                                      uint32_t a) {
    asm volatile("ldmatrix.sync.aligned.m8n8.x4.shared.b16 {%0,%1,%2,%3}, [%4];"
                 : "=r"(r0), "=r"(r1), "=r"(r2), "=r"(r3) : "r"(a));
}
__device__ __forceinline__ void mma16816(float& c0, float& c1, float& c2, float& c3,
                                         uint32_t a0, uint32_t a1, uint32_t a2, uint32_t a3,
                                         uint32_t b0, uint32_t b1) {
    asm volatile("mma.sync.aligned.m16n8k16.row.col.f32.f16.f16.f32 "
                 "{%0,%1,%2,%3},{%4,%5,%6,%7},{%8,%9},{%0,%1,%2,%3};"
                 : "+f"(c0), "+f"(c1), "+f"(c2), "+f"(c3)
                 : "r"(a0), "r"(a1), "r"(a2), "r"(a3), "r"(b0), "r"(b1));
}
__device__ __forceinline__ float fast_tanh(float x) {
    x = fminf(fmaxf(x, -15.f), 15.f);
    float e = __expf(-2.f * x);
    return (1.f - e) * __frcp_rn(1.f + e);
}

// smem per stage buffer: STRIDE 40 halves (80 B rows). A(64 rows) 5120 B, B(64 rows) 5120 B.
#define STRIDE 40
#define OFF_A  0
#define OFF_B  5120
#define BUF_B  10240
#define NSTAGE 4
#define SMEM_BYTES (NSTAGE * BUF_B)      // 40960

// ---------------- fp16 HMMA GEMM, 4-stage cp.async pipeline ----------------
// CTA 64x64, BK=32, 8 warps 4(M)x2(N), warp tile 16x32, ldmatrix feeds.
template <int ACT>  // 0: relu + fp16 out; 1: tanh + fp16 out
__global__ void __launch_bounds__(256) mma_gemm(
    const __half* __restrict__ A, const __half* __restrict__ Bw,
    const float* __restrict__ bias,
    __half* __restrict__ Ch, int K, int Mout)
{
    extern __shared__ char smem[];
    const uint32_t sb = smem_u32(smem);
    const int tid = threadIdx.x, wid = tid >> 5, lid = tid & 31;
    const int rowBase = blockIdx.y * 64;
    const int colBase = blockIdx.x * 64;
    const int warpM = (wid & 3) * 16;
    const int warpN = (wid >> 2) * 32;
    const int grp = lid >> 2, q = lid & 3;

    // cp.async mapping (BK=32): one 16B chunk per thread per array
    const int ar  = tid >> 2;            // row 0..63
    const int acb = (tid & 3) * 8;       // half offset 0/8/16/24

    const __half* gA = A  + (size_t)(rowBase + ar) * K + acb;
    const __half* gB = Bw + (size_t)(colBase + ar) * K + acb;

    const uint32_t sA = sb + OFF_A + (ar * STRIDE + acb) * 2;
    const uint32_t sB = sb + OFF_B + (ar * STRIDE + acb) * 2;

    // ldmatrix lane addressing
    const int sel  = lid >> 3;
    const int lrow = (sel & 1) * 8 + (lid & 7);
    const int lcol = (sel >> 1) * 8;
    const uint32_t aoff  = ((warpM + lrow) * STRIDE + lcol) * 2;
    const uint32_t boff0 = ((warpN + lrow) * STRIDE + lcol) * 2;
    const uint32_t boff1 = ((warpN + 16 + lrow) * STRIDE + lcol) * 2;

    float c[4][4];
#pragma unroll
    for (int ni = 0; ni < 4; ni++)
#pragma unroll
        for (int r = 0; r < 4; r++) c[ni][r] = 0.f;

    const int NK = K >> 5;

    // prologue: stage tiles 0..2
#pragma unroll
    for (int s = 0; s < NSTAGE - 1; s++) {
        if (s < NK) {
            const int k0 = s << 5;
            const uint32_t bo = s * BUF_B;
            cp16(sA + bo, gA + k0);
            cp16(sB + bo, gB + k0);
        }
        asm volatile("cp.async.commit_group;");
    }

    for (int kt = 0; kt < NK; kt++) {
        asm volatile("cp.async.wait_group %0;" :: "n"(NSTAGE - 2));
        __syncthreads();

        if (kt + NSTAGE - 1 < NK) {
            const int k0 = (kt + NSTAGE - 1) << 5;
            const uint32_t bo = ((kt + NSTAGE - 1) & (NSTAGE - 1)) * BUF_B;
            cp16(sA + bo, gA + k0);
            cp16(sB + bo, gB + k0);
        }
        asm volatile("cp.async.commit_group;");

        const uint32_t aBase = sb + (kt & (NSTAGE - 1)) * BUF_B;
#pragma unroll
        for (int kk = 0; kk < 32; kk += 16) {
            const uint32_t kb = kk * 2;
            uint32_t a[4], b[4][2];
            ldsm4(a[0], a[1], a[2], a[3],             aBase + OFF_A + aoff + kb);
            ldsm4(b[0][0], b[1][0], b[0][1], b[1][1], aBase + OFF_B + boff0 + kb);
            ldsm4(b[2][0], b[3][0], b[2][1], b[3][1], aBase + OFF_B + boff1 + kb);
#pragma unroll
            for (int ni = 0; ni < 4; ni++)
                mma16816(c[ni][0], c[ni][1], c[ni][2], c[ni][3],
                         a[0], a[1], a[2], a[3], b[ni][0], b[ni][1]);
        }
    }

    // ---------------- epilogue ----------------
#pragma unroll
    for (int ni = 0; ni < 4; ni++) {
        const int col = colBase + warpN + ni * 8 + q * 2;
        const float bv0 = bias[col], bv1 = bias[col + 1];
        const int row0 = rowBase + warpM + grp;
        float v00 = c[ni][0] + bv0, v01 = c[ni][1] + bv1;
        float v10 = c[ni][2] + bv0, v11 = c[ni][3] + bv1;
        if (ACT == 0) {
            v00 = fmaxf(v00, 0.f); v01 = fmaxf(v01, 0.f);
            v10 = fmaxf(v10, 0.f); v11 = fmaxf(v11, 0.f);
        } else {
            v00 = fast_tanh(v00); v01 = fast_tanh(v01);
            v10 = fast_tanh(v10); v11 = fast_tanh(v11);
        }
        __half2 H0 = __floats2half2_rn(v00, v01);
        __half2 H1 = __floats2half2_rn(v10, v11);
        *(uint32_t*)(Ch + (size_t)row0 * Mout + col) = *(uint32_t*)&H0;
        *(uint32_t*)(Ch + (size_t)(row0 + 8) * Mout + col) = *(uint32_t*)&H1;
    }
}

// ---------------- weight rounding (merged: W0, W1, W2 in one launch) ----------------
__global__ void wround_all(const float* __restrict__ W0, const float* __restrict__ W1,
                           const float* __restrict__ W2,
                           __half* __restrict__ h0, __half* __restrict__ h1,
                           __half* __restrict__ h2) {
    int idx = blockIdx.x * blockDim.x + threadIdx.x;
    const int n0 = H_F * E_F, n1 = n0 + H_F * H_F, n2 = n1 + H_F * H_F;
    if (idx < n0)       h0[idx]      = __float2half_rn(W0[idx]);
    else if (idx < n1)  h1[idx - n0] = __float2half_rn(W1[idx - n0]);
    else if (idx < n2)  h2[idx - n1] = __float2half_rn(W2[idx - n1]);
}
// W3: src row e*10+d -> dst row d*128+e ; also permute b3
__global__ void wround_w3(const float* __restrict__ s, __half* __restrict__ h,
                          const float* __restrict__ b3) {
    int idx = blockIdx.x * blockDim.x + threadIdx.x;
    if (idx >= M3 * H_F) return;
    int r = idx >> 9, k = idx & 511;
    int e = r / D_F, d = r - e * D_F;
    h[(size_t)(d * E_F + e) * H_F + k] = __float2half_rn(s[idx]);
    if (idx < M3) {
        int e2 = idx / D_F, d2 = idx - e2 * D_F;
        g_b3p[d2 * E_F + e2] = b3[idx];
    }
}

// ---------------- spline ----------------
__global__ void spline_kernel(const float* __restrict__ t, const float* __restrict__ x) {
    int col = blockIdx.x * blockDim.x + threadIdx.x;
    if (col >= ND) return;
    int n = col / D_F, d = col % D_F;
    float tv[T_K];
#pragma unroll
    for (int i = 0; i < T_K; i++) tv[i] = t[i];
    float xv[T_K];
#pragma unroll
    for (int i = 0; i < T_K; i++) xv[i] = x[(n * T_K + i) * D_F + d];
    float h[T_K - 1];
#pragma unroll
    for (int i = 0; i < T_K - 1; i++) h[i] = tv[i + 1] - tv[i];
    float cp[T_K], dp[T_K];
    cp[0] = 0.f; dp[0] = 0.f;
#pragma unroll
    for (int i = 1; i < T_K - 1; i++) {
        float rhs = 6.f * ((xv[i + 1] - xv[i]) / h[i] - (xv[i] - xv[i - 1]) / h[i - 1]);
        float m = 2.f * (h[i - 1] + h[i]) - h[i - 1] * cp[i - 1];
        float inv = 1.f / m;
        cp[i] = h[i] * inv;
        dp[i] = (rhs - h[i - 1] * dp[i - 1]) * inv;
    }
    float Mv[T_K];
    Mv[T_K - 1] = 0.f;
#pragma unroll
    for (int i = T_K - 2; i >= 0; i--) Mv[i] = dp[i] - cp[i] * Mv[i + 1];
#pragma unroll
    for (int i = 0; i < T_K; i++) g_M[i * ND + col] = Mv[i];
}

// ---------------- dX/dt ----------------
__global__ void dx_kernel(const float* __restrict__ t, const float* __restrict__ x) {
    int idx = blockIdx.x * blockDim.x + threadIdx.x;
    if (idx >= NPTS * ND) return;
    int pt = idx / ND, col = idx - pt * ND;
    int n = col / D_F, d = col - n * D_F;
    int k = pt >> 2, j = pt & 3;
    float t0 = t[k], t1 = t[k + 1];
    float hs = t1 - t0;
    float s;
    if (j == 0) s = t0;
    else if (j == 1) s = t0 + hs / 3.0f;
    else if (j == 2) s = t0 + 2.0f * hs / 3.0f;
    else s = t1;
    int cnt = 0;
#pragma unroll
    for (int i = 0; i < T_K; i++) cnt += (t[i] <= s) ? 1 : 0;
    int i = min(max(cnt - 1, 0), T_K - 2);
    float hi = t[i + 1] - t[i];
    float xi  = x[(n * T_K + i) * D_F + d];
    float xi1 = x[(n * T_K + i + 1) * D_F + d];
    float Mi  = g_M[i * ND + col];
    float Mi1 = g_M[(i + 1) * ND + col];
    float u = s - t[i];
    float b = (xi1 - xi) / hi - hi * (2.0f * Mi + Mi1) / 6.0f;
    g_dX[idx] = b + Mi * u + (Mi1 - Mi) * (u * u) / (2.0f * hi);
}

// ---------------- z0 ----------------
__global__ void z0_kernel(const float* __restrict__ x, const float* __restrict__ We,
                          const float* __restrict__ be) {
    int idx = blockIdx.x * blockDim.x + threadIdx.x;
    if (idx >= NE) return;
    int n = idx / E_F, e = idx - n * E_F;
    float acc = be[e];
#pragma unroll
    for (int d = 0; d < D_F; d++) acc += x[n * T_K * D_F + d] * We[e * D_F + d];
    g_z[idx] = acc;
    g_zh[idx] = __float2half_rn(acc);
}

// ---------------- fused einsum + RK combine (y3h layout [n][d*128+e]) ----------------
__global__ void vf_combine(const float* __restrict__ t, int k, int mode) {
    int idx = blockIdx.x * blockDim.x + threadIdx.x;
    if (idx >= NE) return;
    int n = idx >> 7, e = idx & 127;
    const __half* y = g_y3h + (size_t)n * M3 + e;
    const float* dx = g_dX + (size_t)(k * 4 + mode) * ND + n * D_F;
    float kv = 0.f;
#pragma unroll
    for (int d = 0; d < D_F; d++) kv += __half2float(y[d * E_F]) * dx[d];
    float hs = t[k + 1] - t[k];
    float z = g_z[idx];
    float zn;
    if (mode == 0)      { g_k1[idx] = kv; zn = z + hs * kv / 3.0f; }
    else if (mode == 1) { g_k2[idx] = kv; zn = z + hs * (kv - g_k1[idx] / 3.0f); }
    else if (mode == 2) { g_k3[idx] = kv; zn = z + hs * (g_k1[idx] - g_k2[idx] + kv); }
    else {
        zn = z + hs * (g_k1[idx] + 3.0f * (g_k2[idx] + g_k3[idx]) + kv) / 8.0f;
        g_z[idx] = zn;
    }
    if (mode == 3) g_zh[idx]   = __float2half_rn(zn);
    else           g_zinh[idx] = __float2half_rn(zn);
}

// ---------------- output with mask ----------------
__global__ void out_kernel(const int* __restrict__ mask, float* __restrict__ out) {
    int idx = blockIdx.x * blockDim.x + threadIdx.x;
    if (idx >= NE) return;
    int n = idx / E_F;
    out[idx] = (mask[n] != 0) ? g_z[idx] : 0.0f;
}

// ---------------- launcher ----------------
extern "C" void kernel_launch(void* const* d_in, const int* in_sizes, int n_in,
                              void* d_out, int out_size) {
    const float* t  = (const float*)d_in[0];
    const float* x  = (const float*)d_in[1];
    const int*   mask = (const int*)d_in[2];
    const float* We = (const float*)d_in[3];
    const float* be = (const float*)d_in[4];
    const float* W0 = (const float*)d_in[5];
    const float* b0 = (const float*)d_in[6];
    const float* W1 = (const float*)d_in[7];
    const float* b1 = (const float*)d_in[8];
    const float* W2 = (const float*)d_in[9];
    const float* b2 = (const float*)d_in[10];
    const float* W3 = (const float*)d_in[11];
    const float* b3 = (const float*)d_in[12];

    cudaFuncSetAttribute(mma_gemm<0>, cudaFuncAttributeMaxDynamicSharedMemorySize, SMEM_BYTES);
    cudaFuncSetAttribute(mma_gemm<1>, cudaFuncAttributeMaxDynamicSharedMemorySize, SMEM_BYTES);

    __half *zh, *zinh, *y0, *y1, *y2, *y3h, *W0r, *W1r, *W2r, *W3r;
    float *b3p;
    cudaGetSymbolAddress((void**)&zh, g_zh);
    cudaGetSymbolAddress((void**)&zinh, g_zinh);
    cudaGetSymbolAddress((void**)&y0, g_y0);
    cudaGetSymbolAddress((void**)&y1, g_y1);
    cudaGetSymbolAddress((void**)&y2, g_y2);
    cudaGetSymbolAddress((void**)&y3h, g_y3h);
    cudaGetSymbolAddress((void**)&W0r, g_W0);    cudaGetSymbolAddress((void**)&W1r, g_W1);
    cudaGetSymbolAddress((void**)&W2r, g_W2);    cudaGetSymbolAddress((void**)&W3r, g_W3);
    cudaGetSymbolAddress((void**)&b3p, g_b3p);

    const int nW = H_F * E_F + 2 * H_F * H_F;
    wround_all<<<(nW + 255) / 256, 256>>>(W0, W1, W2, W0r, W1r, W2r);
    wround_w3<<<(M3 * H_F + 255) / 256, 256>>>(W3, W3r, b3);

    spline_kernel<<<(ND + 255) / 256, 256>>>(t, x);
    dx_kernel<<<(NPTS * ND + 255) / 256, 256>>>(t, x);
    z0_kernel<<<(NE + 255) / 256, 256>>>(x, We, be);

    dim3 gH(H_F / 64, N_AG / 64);   // (8, 32) = 256 CTAs
    dim3 g3(M3 / 64, N_AG / 64);    // (20, 32) = 640 CTAs
    int eb = (NE + 255) / 256;

    for (int k = 0; k < T_K - 1; k++) {
        for (int stage = 0; stage < 4; stage++) {
            const __half* a0 = (stage == 0) ? zh : zinh;
            mma_gemm<0><<<gH, 256, SMEM_BYTES>>>(a0, W0r, b0, y0, E_F, H_F);
            mma_gemm<0><<<gH, 256, SMEM_BYTES>>>(y0, W1r, b1, y1, H_F, H_F);
            mma_gemm<0><<<gH, 256, SMEM_BYTES>>>(y1, W2r, b2, y2, H_F, H_F);
            mma_gemm<1><<<g3, 256, SMEM_BYTES>>>(y2, W3r, b3p, y3h, H_F, M3);
            vf_combine<<<eb, 256>>>(t, k, stage);
        }
    }
    out_kernel<<<eb, 256>>>(mask, (float*)d_out);
}

// round 15
// speedup vs baseline: 2.0960x; 1.4173x over previous
#include <cuda_runtime.h>
#include <cuda_fp16.h>
#include <cstdint>

// ---------------- problem constants ----------------
#define N_AG 2048
#define T_K 16
#define D_F 10
#define E_F 128
#define H_F 512
#define M3 (E_F * D_F)      // 1280
#define ND (N_AG * D_F)
#define NPTS 60
#define NE (N_AG * E_F)

// ---------------- scratch ----------------
__device__ float g_M[T_K * ND];
__device__ float g_dX[NPTS * ND];
__device__ float g_z[NE];
__device__ float g_k1[NE];
__device__ float g_k2[NE];
__device__ float g_k3[NE];
__device__ float g_b3p[M3];
__device__ int   g_nact;
__device__ int   g_perm[N_AG];     // compact -> original
__device__ int   g_inv[N_AG];      // original -> compact (-1 if masked out)

#define H16A __device__ __align__(16) __half
H16A g_y3h[N_AG * M3];             // layout [n][d*128+e], fp16 (compacted rows)
H16A g_zh[NE];
H16A g_zinh[NE];
H16A g_y0[N_AG * H_F];
H16A g_y1[N_AG * H_F];
H16A g_y2[N_AG * H_F];
H16A g_W0[H_F * E_F];
H16A g_W1[H_F * H_F];
H16A g_W2[H_F * H_F];
H16A g_W3[M3 * H_F];               // rows permuted: dst row = d*128+e

// ---------------- helpers ----------------
__device__ __forceinline__ uint32_t smem_u32(const void* p) {
    uint32_t a;
    asm("{ .reg .u64 t; cvta.to.shared.u64 t, %1; cvt.u32.u64 %0, t; }" : "=r"(a) : "l"(p));
    return a;
}
__device__ __forceinline__ void cp16(uint32_t s, const void* g) {
    asm volatile("cp.async.cg.shared.global [%0], [%1], 16;" :: "r"(s), "l"(g));
}
__device__ __forceinline__ void ldsm4(uint32_t& r0, uint32_t& r1, uint32_t& r2, uint32_t& r3,
                                      uint32_t a) {
    asm volatile("ldmatrix.sync.aligned.m8n8.x4.shared.b16 {%0,%1,%2,%3}, [%4];"
                 : "=r"(r0), "=r"(r1), "=r"(r2), "=r"(r3) : "r"(a));
}
__device__ __forceinline__ void mma16816(float& c0, float& c1, float& c2, float& c3,
                                         uint32_t a0, uint32_t a1, uint32_t a2, uint32_t a3,
                                         uint32_t b0, uint32_t b1) {
    asm volatile("mma.sync.aligned.m16n8k16.row.col.f32.f16.f16.f32 "
                 "{%0,%1,%2,%3},{%4,%5,%6,%7},{%8,%9},{%0,%1,%2,%3};"
                 : "+f"(c0), "+f"(c1), "+f"(c2), "+f"(c3)
                 : "r"(a0), "r"(a1), "r"(a2), "r"(a3), "r"(b0), "r"(b1));
}
__device__ __forceinline__ float fast_tanh(float x) {
    x = fminf(fmaxf(x, -15.f), 15.f);
    float e = __expf(-2.f * x);
    return (1.f - e) * __frcp_rn(1.f + e);
}

// smem per stage buffer: STRIDE 40 halves (80 B rows). A(64 rows) 5120 B, B(64 rows) 5120 B.
#define STRIDE 40
#define OFF_A  0
#define OFF_B  5120
#define BUF_B  10240
#define NSTAGE 4
#define SMEM_BYTES (NSTAGE * BUF_B)      // 40960

// ---------------- fp16 HMMA GEMM, 4-stage cp.async pipeline ----------------
// CTA 64x64, BK=32, 8 warps 4(M)x2(N), warp tile 16x32, ldmatrix feeds.
// Rows are COMPACTED active rows; CTAs beyond g_nact early-exit.
template <int ACT>  // 0: relu + fp16 out; 1: tanh + fp16 out
__global__ void __launch_bounds__(256) mma_gemm(
    const __half* __restrict__ A, const __half* __restrict__ Bw,
    const float* __restrict__ bias,
    __half* __restrict__ Ch, int K, int Mout)
{
    const int rowBase = blockIdx.y * 64;
    if (rowBase >= g_nact) return;

    extern __shared__ char smem[];
    const uint32_t sb = smem_u32(smem);
    const int tid = threadIdx.x, wid = tid >> 5, lid = tid & 31;
    const int colBase = blockIdx.x * 64;
    const int warpM = (wid & 3) * 16;
    const int warpN = (wid >> 2) * 32;
    const int grp = lid >> 2, q = lid & 3;

    // cp.async mapping (BK=32): one 16B chunk per thread per array
    const int ar  = tid >> 2;            // row 0..63
    const int acb = (tid & 3) * 8;       // half offset 0/8/16/24

    const __half* gA = A  + (size_t)(rowBase + ar) * K + acb;
    const __half* gB = Bw + (size_t)(colBase + ar) * K + acb;

    const uint32_t sA = sb + OFF_A + (ar * STRIDE + acb) * 2;
    const uint32_t sB = sb + OFF_B + (ar * STRIDE + acb) * 2;

    // ldmatrix lane addressing
    const int sel  = lid >> 3;
    const int lrow = (sel & 1) * 8 + (lid & 7);
    const int lcol = (sel >> 1) * 8;
    const uint32_t aoff  = ((warpM + lrow) * STRIDE + lcol) * 2;
    const uint32_t boff0 = ((warpN + lrow) * STRIDE + lcol) * 2;
    const uint32_t boff1 = ((warpN + 16 + lrow) * STRIDE + lcol) * 2;

    float c[4][4];
#pragma unroll
    for (int ni = 0; ni < 4; ni++)
#pragma unroll
        for (int r = 0; r < 4; r++) c[ni][r] = 0.f;

    const int NK = K >> 5;

    // prologue: stage tiles 0..2
#pragma unroll
    for (int s = 0; s < NSTAGE - 1; s++) {
        if (s < NK) {
            const int k0 = s << 5;
            const uint32_t bo = s * BUF_B;
            cp16(sA + bo, gA + k0);
            cp16(sB + bo, gB + k0);
        }
        asm volatile("cp.async.commit_group;");
    }

    for (int kt = 0; kt < NK; kt++) {
        asm volatile("cp.async.wait_group %0;" :: "n"(NSTAGE - 2));
        __syncthreads();

        if (kt + NSTAGE - 1 < NK) {
            const int k0 = (kt + NSTAGE - 1) << 5;
            const uint32_t bo = ((kt + NSTAGE - 1) & (NSTAGE - 1)) * BUF_B;
            cp16(sA + bo, gA + k0);
            cp16(sB + bo, gB + k0);
        }
        asm volatile("cp.async.commit_group;");

        const uint32_t aBase = sb + (kt & (NSTAGE - 1)) * BUF_B;
#pragma unroll
        for (int kk = 0; kk < 32; kk += 16) {
            const uint32_t kb = kk * 2;
            uint32_t a[4], b[4][2];
            ldsm4(a[0], a[1], a[2], a[3],             aBase + OFF_A + aoff + kb);
            ldsm4(b[0][0], b[1][0], b[0][1], b[1][1], aBase + OFF_B + boff0 + kb);
            ldsm4(b[2][0], b[3][0], b[2][1], b[3][1], aBase + OFF_B + boff1 + kb);
#pragma unroll
            for (int ni = 0; ni < 4; ni++)
                mma16816(c[ni][0], c[ni][1], c[ni][2], c[ni][3],
                         a[0], a[1], a[2], a[3], b[ni][0], b[ni][1]);
        }
    }

    // ---------------- epilogue ----------------
#pragma unroll
    for (int ni = 0; ni < 4; ni++) {
        const int col = colBase + warpN + ni * 8 + q * 2;
        const float bv0 = bias[col], bv1 = bias[col + 1];
        const int row0 = rowBase + warpM + grp;
        float v00 = c[ni][0] + bv0, v01 = c[ni][1] + bv1;
        float v10 = c[ni][2] + bv0, v11 = c[ni][3] + bv1;
        if (ACT == 0) {
            v00 = fmaxf(v00, 0.f); v01 = fmaxf(v01, 0.f);
            v10 = fmaxf(v10, 0.f); v11 = fmaxf(v11, 0.f);
        } else {
            v00 = fast_tanh(v00); v01 = fast_tanh(v01);
            v10 = fast_tanh(v10); v11 = fast_tanh(v11);
        }
        __half2 H0 = __floats2half2_rn(v00, v01);
        __half2 H1 = __floats2half2_rn(v10, v11);
        *(uint32_t*)(Ch + (size_t)row0 * Mout + col) = *(uint32_t*)&H0;
        *(uint32_t*)(Ch + (size_t)(row0 + 8) * Mout + col) = *(uint32_t*)&H1;
    }
}

// ---------------- mask compaction (deterministic prefix count) ----------------
__global__ void mask_compact(const int* __restrict__ mask) {
    __shared__ int sm[N_AG];
    for (int i = threadIdx.x; i < N_AG; i += blockDim.x) sm[i] = (mask[i] != 0) ? 1 : 0;
    __syncthreads();
    int n = blockIdx.x * blockDim.x + threadIdx.x;
    if (n >= N_AG) return;
    int pos = 0;
    for (int i = 0; i < n; i++) pos += sm[i];
    g_inv[n] = sm[n] ? pos : -1;
    if (sm[n]) g_perm[pos] = n;
    if (n == N_AG - 1) g_nact = pos + sm[n];
}

// ---------------- weight rounding (merged: W0, W1, W2 in one launch) ----------------
__global__ void wround_all(const float* __restrict__ W0, const float* __restrict__ W1,
                           const float* __restrict__ W2,
                           __half* __restrict__ h0, __half* __restrict__ h1,
                           __half* __restrict__ h2) {
    int idx = blockIdx.x * blockDim.x + threadIdx.x;
    const int n0 = H_F * E_F, n1 = n0 + H_F * H_F, n2 = n1 + H_F * H_F;
    if (idx < n0)       h0[idx]      = __float2half_rn(W0[idx]);
    else if (idx < n1)  h1[idx - n0] = __float2half_rn(W1[idx - n0]);
    else if (idx < n2)  h2[idx - n1] = __float2half_rn(W2[idx - n1]);
}
// W3: src row e*10+d -> dst row d*128+e ; also permute b3
__global__ void wround_w3(const float* __restrict__ s, __half* __restrict__ h,
                          const float* __restrict__ b3) {
    int idx = blockIdx.x * blockDim.x + threadIdx.x;
    if (idx >= M3 * H_F) return;
    int r = idx >> 9, k = idx & 511;
    int e = r / D_F, d = r - e * D_F;
    h[(size_t)(d * E_F + e) * H_F + k] = __float2half_rn(s[idx]);
    if (idx < M3) {
        int e2 = idx / D_F, d2 = idx - e2 * D_F;
        g_b3p[d2 * E_F + e2] = b3[idx];
    }
}

// ---------------- spline (original row layout) ----------------
__global__ void spline_kernel(const float* __restrict__ t, const float* __restrict__ x) {
    int col = blockIdx.x * blockDim.x + threadIdx.x;
    if (col >= ND) return;
    int n = col / D_F, d = col % D_F;
    float tv[T_K];
#pragma unroll
    for (int i = 0; i < T_K; i++) tv[i] = t[i];
    float xv[T_K];
#pragma unroll
    for (int i = 0; i < T_K; i++) xv[i] = x[(n * T_K + i) * D_F + d];
    float h[T_K - 1];
#pragma unroll
    for (int i = 0; i < T_K - 1; i++) h[i] = tv[i + 1] - tv[i];
    float cp[T_K], dp[T_K];
    cp[0] = 0.f; dp[0] = 0.f;
#pragma unroll
    for (int i = 1; i < T_K - 1; i++) {
        float rhs = 6.f * ((xv[i + 1] - xv[i]) / h[i] - (xv[i] - xv[i - 1]) / h[i - 1]);
        float m = 2.f * (h[i - 1] + h[i]) - h[i - 1] * cp[i - 1];
        float inv = 1.f / m;
        cp[i] = h[i] * inv;
        dp[i] = (rhs - h[i - 1] * dp[i - 1]) * inv;
    }
    float Mv[T_K];
    Mv[T_K - 1] = 0.f;
#pragma unroll
    for (int i = T_K - 2; i >= 0; i--) Mv[i] = dp[i] - cp[i] * Mv[i + 1];
#pragma unroll
    for (int i = 0; i < T_K; i++) g_M[i * ND + col] = Mv[i];
}

// ---------------- dX/dt (original row layout) ----------------
__global__ void dx_kernel(const float* __restrict__ t, const float* __restrict__ x) {
    int idx = blockIdx.x * blockDim.x + threadIdx.x;
    if (idx >= NPTS * ND) return;
    int pt = idx / ND, col = idx - pt * ND;
    int n = col / D_F, d = col - n * D_F;
    int k = pt >> 2, j = pt & 3;
    float t0 = t[k], t1 = t[k + 1];
    float hs = t1 - t0;
    float s;
    if (j == 0) s = t0;
    else if (j == 1) s = t0 + hs / 3.0f;
    else if (j == 2) s = t0 + 2.0f * hs / 3.0f;
    else s = t1;
    int cnt = 0;
#pragma unroll
    for (int i = 0; i < T_K; i++) cnt += (t[i] <= s) ? 1 : 0;
    int i = min(max(cnt - 1, 0), T_K - 2);
    float hi = t[i + 1] - t[i];
    float xi  = x[(n * T_K + i) * D_F + d];
    float xi1 = x[(n * T_K + i + 1) * D_F + d];
    float Mi  = g_M[i * ND + col];
    float Mi1 = g_M[(i + 1) * ND + col];
    float u = s - t[i];
    float b = (xi1 - xi) / hi - hi * (2.0f * Mi + Mi1) / 6.0f;
    g_dX[idx] = b + Mi * u + (Mi1 - Mi) * (u * u) / (2.0f * hi);
}

// ---------------- z0 (compacted rows) ----------------
__global__ void z0_kernel(const float* __restrict__ x, const float* __restrict__ We,
                          const float* __restrict__ be) {
    int idx = blockIdx.x * blockDim.x + threadIdx.x;
    if (idx >= NE) return;
    int n = idx >> 7;
    if (n >= g_nact) return;
    int e = idx & 127;
    int orig = g_perm[n];
    float acc = be[e];
#pragma unroll
    for (int d = 0; d < D_F; d++) acc += x[orig * T_K * D_F + d] * We[e * D_F + d];
    g_z[idx] = acc;
    g_zh[idx] = __float2half_rn(acc);
}

// ---------------- fused einsum + RK combine (compacted rows) ----------------
__global__ void vf_combine(const float* __restrict__ t, int k, int mode) {
    int idx = blockIdx.x * blockDim.x + threadIdx.x;
    if (idx >= NE) return;
    int n = idx >> 7;
    if (n >= g_nact) return;
    int e = idx & 127;
    int orig = g_perm[n];
    const __half* y = g_y3h + (size_t)n * M3 + e;
    const float* dx = g_dX + (size_t)(k * 4 + mode) * ND + orig * D_F;
    float kv = 0.f;
#pragma unroll
    for (int d = 0; d < D_F; d++) kv += __half2float(y[d * E_F]) * dx[d];
    float hs = t[k + 1] - t[k];
    float z = g_z[idx];
    float zn;
    if (mode == 0)      { g_k1[idx] = kv; zn = z + hs * kv / 3.0f; }
    else if (mode == 1) { g_k2[idx] = kv; zn = z + hs * (kv - g_k1[idx] / 3.0f); }
    else if (mode == 2) { g_k3[idx] = kv; zn = z + hs * (g_k1[idx] - g_k2[idx] + kv); }
    else {
        zn = z + hs * (g_k1[idx] + 3.0f * (g_k2[idx] + g_k3[idx]) + kv) / 8.0f;
        g_z[idx] = zn;
    }
    if (mode == 3) g_zh[idx]   = __float2half_rn(zn);
    else           g_zinh[idx] = __float2half_rn(zn);
}

// ---------------- output: scatter compacted z by mask ----------------
__global__ void out_kernel(float* __restrict__ out) {
    int idx = blockIdx.x * blockDim.x + threadIdx.x;
    if (idx >= NE) return;
    int n = idx >> 7, e = idx & 127;
    int p = g_inv[n];
    out[idx] = (p >= 0) ? g_z[p * E_F + e] : 0.0f;
}

// ---------------- launcher ----------------
extern "C" void kernel_launch(void* const* d_in, const int* in_sizes, int n_in,
                              void* d_out, int out_size) {
    const float* t  = (const float*)d_in[0];
    const float* x  = (const float*)d_in[1];
    const int*   mask = (const int*)d_in[2];
    const float* We = (const float*)d_in[3];
    const float* be = (const float*)d_in[4];
    const float* W0 = (const float*)d_in[5];
    const float* b0 = (const float*)d_in[6];
    const float* W1 = (const float*)d_in[7];
    const float* b1 = (const float*)d_in[8];
    const float* W2 = (const float*)d_in[9];
    const float* b2 = (const float*)d_in[10];
    const float* W3 = (const float*)d_in[11];
    const float* b3 = (const float*)d_in[12];

    cudaFuncSetAttribute(mma_gemm<0>, cudaFuncAttributeMaxDynamicSharedMemorySize, SMEM_BYTES);
    cudaFuncSetAttribute(mma_gemm<1>, cudaFuncAttributeMaxDynamicSharedMemorySize, SMEM_BYTES);

    __half *zh, *zinh, *y0, *y1, *y2, *y3h, *W0r, *W1r, *W2r, *W3r;
    float *b3p;
    cudaGetSymbolAddress((void**)&zh, g_zh);
    cudaGetSymbolAddress((void**)&zinh, g_zinh);
    cudaGetSymbolAddress((void**)&y0, g_y0);
    cudaGetSymbolAddress((void**)&y1, g_y1);
    cudaGetSymbolAddress((void**)&y2, g_y2);
    cudaGetSymbolAddress((void**)&y3h, g_y3h);
    cudaGetSymbolAddress((void**)&W0r, g_W0);    cudaGetSymbolAddress((void**)&W1r, g_W1);
    cudaGetSymbolAddress((void**)&W2r, g_W2);    cudaGetSymbolAddress((void**)&W3r, g_W3);
    cudaGetSymbolAddress((void**)&b3p, g_b3p);

    const int nW = H_F * E_F + 2 * H_F * H_F;
    wround_all<<<(nW + 255) / 256, 256>>>(W0, W1, W2, W0r, W1r, W2r);
    wround_w3<<<(M3 * H_F + 255) / 256, 256>>>(W3, W3r, b3);

    mask_compact<<<N_AG / 256, 256>>>(mask);
    spline_kernel<<<(ND + 255) / 256, 256>>>(t, x);
    dx_kernel<<<(NPTS * ND + 255) / 256, 256>>>(t, x);
    z0_kernel<<<(NE + 255) / 256, 256>>>(x, We, be);

    dim3 gH(H_F / 64, N_AG / 64);   // (8, 32); ~half the y-tiles early-exit
    dim3 g3(M3 / 64, N_AG / 64);    // (20, 32)
    int eb = (NE + 255) / 256;

    for (int k = 0; k < T_K - 1; k++) {
        for (int stage = 0; stage < 4; stage++) {
            const __half* a0 = (stage == 0) ? zh : zinh;
            mma_gemm<0><<<gH, 256, SMEM_BYTES>>>(a0, W0r, b0, y0, E_F, H_F);
            mma_gemm<0><<<gH, 256, SMEM_BYTES>>>(y0, W1r, b1, y1, H_F, H_F);
            mma_gemm<0><<<gH, 256, SMEM_BYTES>>>(y1, W2r, b2, y2, H_F, H_F);
            mma_gemm<1><<<g3, 256, SMEM_BYTES>>>(y2, W3r, b3p, y3h, H_F, M3);
            vf_combine<<<eb, 256>>>(t, k, stage);
        }
    }
    out_kernel<<<eb, 256>>>((float*)d_out);
}